// round 13
// baseline (speedup 1.0000x reference)
#include <cuda_runtime.h>
#include <stdint.h>

// ---------------------------------------------------------------------------
// octree_level emulating the reference's INT32-key overflow semantics
// (JAX x64 disabled): key32 = ((px mod 256)<<24)|(py<<12)|pz signed.
//  - unique sorted SIGNED: wrapped (pxm>=128) keys first -> rows (-1,-1,-1),
//    occupancy 0 (valid = pk>=0 is false).
//  - valid rows: coords (pxm, py, pz) with pxm in [0,128).
//  - occupancy: child match on (x mod 256, y, z)  -> leaf lights slot
//    (x&1,y&1,z&1) of aliased parent ((x&255)>>1, y>>1, z>>1) IF present.
// Bitmap bit index = ((pxm^128)<<18)|(py<<9)|pz : ascending == signed order.
// Output planar: [0,3n) parent rows (pads/fills -1), [3n,11n) occupancy.
// Deterministic, graph-capturable, allocation-free.
// ---------------------------------------------------------------------------

#define PB_WORDS    (1u << 21)                 // 2^26 bits / 32  (8 MB)
#define CHUNK_WORDS 1024u
#define NCHUNKS     (PB_WORDS / CHUNK_WORDS)   // 2048
#define CMASK_WORDS (1u << 20)

__device__ __align__(16) unsigned g_pbm[PB_WORDS];
__device__ unsigned g_wordoff[PB_WORDS];
__device__ unsigned g_partial[NCHUNKS];
__device__ unsigned g_chunkoff[NCHUNKS];
__device__ unsigned g_M;
__device__ __align__(16) unsigned g_cmask[CMASK_WORDS];

__global__ void k_zero() {
    unsigned i = blockIdx.x * blockDim.x + threadIdx.x;
    uint4 z = make_uint4(0u, 0u, 0u, 0u);
    if (i < PB_WORDS / 4)    ((uint4*)g_pbm)[i] = z;
    if (i < CMASK_WORDS / 4) ((uint4*)g_cmask)[i] = z;
}

// K1: mark each leaf's OWN parent (int32-wrapped key -> signed-order index)
__global__ void k_mark(const float* __restrict__ leaf, int n) {
    int i = blockIdx.x * blockDim.x + threadIdx.x;
    if (i >= n) return;
    int x = (int)leaf[3 * i + 0];
    int y = (int)leaf[3 * i + 1];
    int z = (int)leaf[3 * i + 2];
    x = min(max(x, 0), 1023); y = min(max(y, 0), 1023); z = min(max(z, 0), 1023);
    unsigned t = (((unsigned)(x >> 1)) & 255u) ^ 128u;    // pxm ^ 128
    unsigned idx = (t << 18) | ((unsigned)(y >> 1) << 9) | (unsigned)(z >> 1);
    atomicOr(&g_pbm[idx >> 5], 1u << (idx & 31u));
}

// P1: per-chunk popcount
__global__ void k_count() {
    __shared__ unsigned sh[256];
    unsigned t = threadIdx.x;
    const uint4* base = ((const uint4*)g_pbm) + blockIdx.x * (CHUNK_WORDS / 4);
    uint4 w = base[t];
    unsigned s = __popc(w.x) + __popc(w.y) + __popc(w.z) + __popc(w.w);
    sh[t] = s; __syncthreads();
    for (int o = 128; o > 0; o >>= 1) {
        if (t < (unsigned)o) sh[t] += sh[t + o];
        __syncthreads();
    }
    if (t == 0) g_partial[blockIdx.x] = sh[0];
}

// P2: single-block exclusive scan of 2048 chunk counts; total -> g_M
__global__ void k_scan() {
    __shared__ unsigned sh[1024];
    unsigned t = threadIdx.x;
    unsigned v0 = g_partial[2 * t + 0], v1 = g_partial[2 * t + 1];
    unsigned s = v0 + v1;
    sh[t] = s; __syncthreads();
    for (int o = 1; o < 1024; o <<= 1) {
        unsigned add = (t >= (unsigned)o) ? sh[t - o] : 0u;
        __syncthreads();
        sh[t] += add;
        __syncthreads();
    }
    unsigned excl = sh[t] - s;
    g_chunkoff[2 * t + 0] = excl;
    g_chunkoff[2 * t + 1] = excl + v0;
    if (t == 1023) g_M = sh[1023];
}

// P3a: per-word rank offsets + parent rows (invalid -> -1, valid -> coords)
__global__ void k_emit(float* __restrict__ outP, int n) {
    __shared__ unsigned sh[256];
    unsigned b = blockIdx.x, t = threadIdx.x;
    unsigned w0 = b * CHUNK_WORDS + t * 4u;
    const uint4* base = ((const uint4*)g_pbm) + b * (CHUNK_WORDS / 4);
    uint4 w = base[t];
    unsigned words[4] = { w.x, w.y, w.z, w.w };
    unsigned s = __popc(w.x) + __popc(w.y) + __popc(w.z) + __popc(w.w);
    sh[t] = s; __syncthreads();
    for (int o = 1; o < 256; o <<= 1) {
        unsigned add = (t >= (unsigned)o) ? sh[t - o] : 0u;
        __syncthreads();
        sh[t] += add;
        __syncthreads();
    }
    unsigned off = g_chunkoff[b] + sh[t] - s;
#pragma unroll
    for (int j = 0; j < 4; j++) {
        unsigned wi = w0 + (unsigned)j;
        g_wordoff[wi] = off;
        unsigned m = words[j];
        while (m) {
            int bit = __ffs((int)m) - 1;
            m &= m - 1u;
            if (outP && off < (unsigned)n) {
                unsigned idx = wi * 32u + (unsigned)bit;
                unsigned tt = idx >> 18;
                float* o3 = outP + 3ull * off;
                if (tt < 128u) {                       // wrapped-negative key
                    o3[0] = -1.0f; o3[1] = -1.0f; o3[2] = -1.0f;
                } else {
                    o3[0] = (float)(tt - 128u);        // pxm in [0,128)
                    o3[1] = (float)((idx >> 9) & 511u);
                    o3[2] = (float)(idx & 511u);
                }
            }
            off++;
        }
    }
}

// P3b: leaf lights slot of ALIASED parent ((x&255)>>1, y>>1, z>>1) if present
__global__ void k_scatter(const float* __restrict__ leaf, int n) {
    int i = blockIdx.x * blockDim.x + threadIdx.x;
    if (i >= n) return;
    int x = (int)leaf[3 * i + 0];
    int y = (int)leaf[3 * i + 1];
    int z = (int)leaf[3 * i + 2];
    x = min(max(x, 0), 1023); y = min(max(y, 0), 1023); z = min(max(z, 0), 1023);
    unsigned pxm = ((unsigned)x & 255u) >> 1;             // aliased parent x, <128
    unsigned t2 = pxm + 128u;                             // ^128 (valid zone)
    unsigned idx = (t2 << 18) | ((unsigned)(y >> 1) << 9) | (unsigned)(z >> 1);
    unsigned w = idx >> 5, b = idx & 31u;
    unsigned word = g_pbm[w];
    if (!((word >> b) & 1u)) return;                      // parent not in table
    unsigned r = g_wordoff[w] + (unsigned)__popc(word & ((1u << b) - 1u));
    if (r >= (unsigned)n) return;
    unsigned c = ((unsigned)(x & 1) << 2) | ((unsigned)(y & 1) << 1) | (unsigned)(z & 1);
    atomicOr(&g_cmask[r >> 2], (1u << c) << ((r & 3u) * 8u));
}

// P4: fill tail rows with -1; expand occupancy (invalid rows stay all-zero)
__global__ void k_finalize(float* __restrict__ outP, float* __restrict__ outO, int n) {
    int r = blockIdx.x * blockDim.x + threadIdx.x;
    if (r >= n) return;
    unsigned M = g_M;
    unsigned mask = 0u;
    if ((unsigned)r < M) {
        mask = (g_cmask[r >> 2] >> ((r & 3) * 8)) & 0xffu;
    } else if (outP) {
        float* o3 = outP + 3ull * r;
        o3[0] = -1.0f; o3[1] = -1.0f; o3[2] = -1.0f;
    }
    if (outO) {
        float* o = outO + 8ull * r;
        if ((((uintptr_t)o) & 15u) == 0u) {
            ((float4*)o)[0] = make_float4((float)(mask & 1u), (float)((mask >> 1) & 1u),
                                          (float)((mask >> 2) & 1u), (float)((mask >> 3) & 1u));
            ((float4*)o)[1] = make_float4((float)((mask >> 4) & 1u), (float)((mask >> 5) & 1u),
                                          (float)((mask >> 6) & 1u), (float)((mask >> 7) & 1u));
        } else {
#pragma unroll
            for (int c = 0; c < 8; c++) o[c] = (float)((mask >> c) & 1u);
        }
    }
}

extern "C" void kernel_launch(void* const* d_in, const int* in_sizes, int n_in,
                              void* d_out, int out_size) {
    (void)n_in;
    const float* leaf = (const float*)d_in[0];
    long long in0 = (long long)in_sizes[0];
    long long os = (long long)out_size;
    long long nll = (in0 % 3 == 0) ? in0 / 3 : ((os % 11 == 0) ? os / 11 : in0 / 3);
    int n = (int)nll;

    float* out = (float*)d_out;
    float* outP = out;              // [0,3n): parent rows (signed-key order)
    float* outO = out + 3ll * n;    // [3n,11n): occupancy

    const int TB = 256;
    int gb = (n + TB - 1) / TB;

    k_zero<<<(PB_WORDS / 4 + TB - 1) / TB, TB>>>();
    k_mark<<<gb, TB>>>(leaf, n);
    k_count<<<NCHUNKS, 256>>>();
    k_scan<<<1, 1024>>>();
    k_emit<<<NCHUNKS, 256>>>(outP, n);
    k_scatter<<<gb, TB>>>(leaf, n);
    k_finalize<<<gb, TB>>>(outP, outO, n);
}

// round 14
// speedup vs baseline: 1.1384x; 1.1384x over previous
#include <cuda_runtime.h>
#include <stdint.h>

// ---------------------------------------------------------------------------
// octree_level with int32-key-overflow semantics (verified R13, rel=0).
// R14 optimizations: fused prefill (output + bitmap), direct 1.0f occupancy
// stores (cmask + finalize eliminated), shuffle-based scan, u16 word offsets.
// 6 launches. Deterministic, graph-capturable, allocation-free.
// ---------------------------------------------------------------------------

#define PB_WORDS    (1u << 21)                 // 2^26 bits / 32  (8 MB)
#define CHUNK_WORDS 1024u
#define NCHUNKS     (PB_WORDS / CHUNK_WORDS)   // 2048

__device__ __align__(16) unsigned g_pbm[PB_WORDS];
__device__ unsigned short g_woff16[PB_WORDS];  // rank offset relative to chunk
__device__ unsigned g_partial[NCHUNKS];
__device__ unsigned g_chunkoff[NCHUNKS];
__device__ unsigned g_M;

// F: fused fill — zero bitmap, parent region = -1, occupancy region = 0
__global__ void k_fill(float* __restrict__ out, long long n3, long long n11) {
    long long i = (long long)blockIdx.x * blockDim.x + threadIdx.x;
    if (i < PB_WORDS / 4) ((uint4*)g_pbm)[i] = make_uint4(0u, 0u, 0u, 0u);
    long long e = i * 4;
    if (e + 3 < n11) {
        float4 v;
        v.x = (e     < n3) ? -1.0f : 0.0f;
        v.y = (e + 1 < n3) ? -1.0f : 0.0f;
        v.z = (e + 2 < n3) ? -1.0f : 0.0f;
        v.w = (e + 3 < n3) ? -1.0f : 0.0f;
        ((float4*)out)[i] = v;
    } else if (e < n11) {
        for (long long k = e; k < n11; k++) out[k] = (k < n3) ? -1.0f : 0.0f;
    }
}

// K1: mark each leaf's parent (int32-wrapped key -> signed-order bit index)
__global__ void k_mark(const float* __restrict__ leaf, int n) {
    int i = blockIdx.x * blockDim.x + threadIdx.x;
    if (i >= n) return;
    int x = (int)leaf[3 * i + 0];
    int y = (int)leaf[3 * i + 1];
    int z = (int)leaf[3 * i + 2];
    x = min(max(x, 0), 1023); y = min(max(y, 0), 1023); z = min(max(z, 0), 1023);
    unsigned t = (((unsigned)(x >> 1)) & 255u) ^ 128u;    // pxm ^ 128
    unsigned idx = (t << 18) | ((unsigned)(y >> 1) << 9) | (unsigned)(z >> 1);
    atomicOr(&g_pbm[idx >> 5], 1u << (idx & 31u));
}

// P1: per-chunk popcount (256 thr x uint4 = 1024 words)
__global__ void k_count() {
    __shared__ unsigned sh[256];
    unsigned t = threadIdx.x;
    const uint4* base = ((const uint4*)g_pbm) + blockIdx.x * (CHUNK_WORDS / 4);
    uint4 w = base[t];
    unsigned s = __popc(w.x) + __popc(w.y) + __popc(w.z) + __popc(w.w);
    sh[t] = s; __syncthreads();
    for (int o = 128; o > 0; o >>= 1) {
        if (t < (unsigned)o) sh[t] += sh[t + o];
        __syncthreads();
    }
    if (t == 0) g_partial[blockIdx.x] = sh[0];
}

// P2: shuffle-based exclusive scan of 2048 chunk counts (2 syncs); total -> g_M
__global__ void k_scan() {
    __shared__ unsigned wsum[32];
    unsigned t = threadIdx.x, lane = t & 31u, wid = t >> 5;
    unsigned v0 = g_partial[2 * t + 0], v1 = g_partial[2 * t + 1];
    unsigned s = v0 + v1;
    unsigned x = s;
#pragma unroll
    for (int o = 1; o < 32; o <<= 1) {
        unsigned y = __shfl_up_sync(0xffffffffu, x, o);
        if (lane >= (unsigned)o) x += y;
    }
    if (lane == 31u) wsum[wid] = x;
    __syncthreads();
    if (wid == 0) {
        unsigned w = wsum[lane];
#pragma unroll
        for (int o = 1; o < 32; o <<= 1) {
            unsigned y = __shfl_up_sync(0xffffffffu, w, o);
            if (lane >= (unsigned)o) w += y;
        }
        wsum[lane] = w;
    }
    __syncthreads();
    unsigned base = ((wid > 0u) ? wsum[wid - 1] : 0u) + x - s;   // exclusive
    g_chunkoff[2 * t + 0] = base;
    g_chunkoff[2 * t + 1] = base + v0;
    if (t == 1023u) g_M = wsum[31];
}

// P3a: u16 chunk-relative word offsets + parent rows (wrapped -> -1)
__global__ void k_emit(float* __restrict__ outP, int n) {
    __shared__ unsigned sh[256];
    unsigned b = blockIdx.x, t = threadIdx.x;
    unsigned w0 = b * CHUNK_WORDS + t * 4u;
    const uint4* base = ((const uint4*)g_pbm) + b * (CHUNK_WORDS / 4);
    uint4 w = base[t];
    unsigned words[4] = { w.x, w.y, w.z, w.w };
    unsigned s = __popc(w.x) + __popc(w.y) + __popc(w.z) + __popc(w.w);
    sh[t] = s; __syncthreads();
    for (int o = 1; o < 256; o <<= 1) {
        unsigned add = (t >= (unsigned)o) ? sh[t - o] : 0u;
        __syncthreads();
        sh[t] += add;
        __syncthreads();
    }
    unsigned rel = sh[t] - s;                       // chunk-relative
    unsigned chunkbase = g_chunkoff[b];
#pragma unroll
    for (int j = 0; j < 4; j++) {
        unsigned wi = w0 + (unsigned)j;
        g_woff16[wi] = (unsigned short)rel;
        unsigned m = words[j];
        while (m) {
            int bit = __ffs((int)m) - 1;
            m &= m - 1u;
            unsigned off = chunkbase + rel;
            if (outP && off < (unsigned)n) {
                unsigned idx = wi * 32u + (unsigned)bit;
                unsigned tt = idx >> 18;
                if (tt >= 128u) {                   // valid (non-wrapped) key
                    float* o3 = outP + 3ull * off;
                    o3[0] = (float)(tt - 128u);
                    o3[1] = (float)((idx >> 9) & 511u);
                    o3[2] = (float)(idx & 511u);
                }
                // wrapped rows: prefilled -1 already correct
            }
            rel++;
        }
    }
}

// P3b: leaf lights occupancy slot directly (idempotent 1.0f stores)
__global__ void k_scatter(const float* __restrict__ leaf,
                          float* __restrict__ outO, int n) {
    int i = blockIdx.x * blockDim.x + threadIdx.x;
    if (i >= n) return;
    int x = (int)leaf[3 * i + 0];
    int y = (int)leaf[3 * i + 1];
    int z = (int)leaf[3 * i + 2];
    x = min(max(x, 0), 1023); y = min(max(y, 0), 1023); z = min(max(z, 0), 1023);
    unsigned pxm = ((unsigned)x & 255u) >> 1;             // aliased parent x
    unsigned t2 = pxm + 128u;                             // valid zone (^128)
    unsigned idx = (t2 << 18) | ((unsigned)(y >> 1) << 9) | (unsigned)(z >> 1);
    unsigned w = idx >> 5, b = idx & 31u;
    unsigned word = g_pbm[w];
    if (!((word >> b) & 1u)) return;                      // parent absent
    unsigned r = g_chunkoff[w >> 10] + (unsigned)g_woff16[w]
               + (unsigned)__popc(word & ((1u << b) - 1u));
    if (r >= (unsigned)n) return;
    unsigned c = ((unsigned)(x & 1) << 2) | ((unsigned)(y & 1) << 1) | (unsigned)(z & 1);
    outO[8ull * r + c] = 1.0f;
}

extern "C" void kernel_launch(void* const* d_in, const int* in_sizes, int n_in,
                              void* d_out, int out_size) {
    (void)n_in;
    const float* leaf = (const float*)d_in[0];
    long long in0 = (long long)in_sizes[0];
    long long os = (long long)out_size;
    long long nll = (in0 % 3 == 0) ? in0 / 3 : ((os % 11 == 0) ? os / 11 : in0 / 3);
    int n = (int)nll;

    float* out = (float*)d_out;
    float* outP = out;              // [0,3n): parent rows (signed-key order)
    float* outO = out + 3ll * n;    // [3n,11n): occupancy

    const int TB = 256;
    int gb = (n + TB - 1) / TB;
    long long n3 = 3ll * n, n11 = 11ll * n;
    long long fillq = (n11 + 3) / 4;
    long long fillt = fillq > (long long)(PB_WORDS / 4) ? fillq : (long long)(PB_WORDS / 4);

    k_fill<<<(unsigned)((fillt + TB - 1) / TB), TB>>>(out, n3, n11);
    k_mark<<<gb, TB>>>(leaf, n);
    k_count<<<NCHUNKS, 256>>>();
    k_scan<<<1, 1024>>>();
    k_emit<<<NCHUNKS, 256>>>(outP, n);
    k_scatter<<<gb, TB>>>(leaf, outO, n);
}